// round 9
// baseline (speedup 1.0000x reference)
#include <cuda_runtime.h>

#define HH 512
#define WW 512
#define BB 16
#define HW (HH * WW)
#define RPB 4
#define GRIDX (HH / RPB)      // 128
#define NTHR  128
#define FULLM 0xffffffffu

__device__ __forceinline__ float ex2f(float x) {
    float r; asm("ex2.approx.f32 %0, %1;" : "=f"(r) : "f"(x)); return r;
}

// contribution = (ex2(d2*C2E)*wxy - eps) * (ya-yb)^2
// C2E = -log2(e)/(2*sigma^2) folded so ex2 is used directly (no log2e mul)
__device__ __forceinline__ float shift_term(float a0, float a1, float a2,
                                            float b0, float b1, float b2,
                                            float ya, float yb, float wxy) {
    const float C2E = -32.059889797532520f;   // -1.4426950408889634 / (2*0.15^2)
    float dx0 = a0 - b0, dx1 = a1 - b1, dx2 = a2 - b2;
    float d2 = dx0 * dx0;
    d2 = fmaf(dx1, dx1, d2);
    d2 = fmaf(dx2, dx2, d2);
    float e = ex2f(d2 * C2E);
    float m = fmaf(e, wxy, -0.01f);           // SUB_EPS
    float dy = ya - yb;
    return m * (dy * dy);
}

__global__ void __launch_bounds__(NTHR, 6)
crf_loss_kernel(const float* __restrict__ ypr,
                const float* __restrict__ img,
                const int*   __restrict__ icls,
                float* __restrict__ out)
{
    const int b = blockIdx.y;
    if (icls[b] == 0) return;                  // sel == 0: no contribution

    const int tid  = threadIdx.x;
    const int lane = tid & 31;
    const int w0   = tid << 2;                 // 4 px/thread, 128 thr = full row
    const int r0   = blockIdx.x * RPB;

    const float* Y = ypr + (size_t)(2 * b + 1) * HW;
    const float* I = img + (size_t)(3 * b)     * HW;   // planes at +0,+HW,+2HW

    const bool lastLane  = (lane == 31);
    const bool firstLane = (lane == 0);
    const bool hasR = (w0 + 4 < WW);           // false only tid 127
    const bool hasL = (w0 > 0);                // false only tid 0

    const float WXY1 = 0.60653065971263342f;   // exp(-0.5)
    const float WXY2 = 0.36787944117144233f;   // exp(-1.0)

    // raw row load: 4 float4 + boundary edge scalars (lanes 0/31 only)
#define LOADROW(ROW, vy, va, vb, vc, eR, eL)                                   \
    {                                                                          \
        const int off = (ROW) * WW + w0;                                       \
        float4 t;                                                              \
        t = *(const float4*)(Y + off);        vy[0]=t.x; vy[1]=t.y; vy[2]=t.z; vy[3]=t.w; \
        t = *(const float4*)(I + off);        va[0]=t.x; va[1]=t.y; va[2]=t.z; va[3]=t.w; \
        t = *(const float4*)(I + off + HW);   vb[0]=t.x; vb[1]=t.y; vb[2]=t.z; vb[3]=t.w; \
        t = *(const float4*)(I + off + 2*HW); vc[0]=t.x; vc[1]=t.y; vc[2]=t.z; vc[3]=t.w; \
        if (lastLane && hasR) {                                                \
            eR[0] = Y[off + 4];        eR[1] = I[off + 4];                     \
            eR[2] = I[off + 4 + HW];   eR[3] = I[off + 4 + 2*HW];              \
        }                                                                      \
        if (firstLane && hasL) {                                               \
            eL[0] = Y[off - 1];        eL[1] = I[off - 1];                     \
            eL[2] = I[off - 1 + HW];   eL[3] = I[off - 1 + 2*HW];              \
        }                                                                      \
    }

    // ---- prologue: load rows r0 (cur) and r0+1 (next) back-to-back ----
    float cy[4], ca[4], cb[4], cc[4];
    float ceR[4] = {0,0,0,0}, ceL[4] = {0,0,0,0};
    LOADROW(r0, cy, ca, cb, cc, ceR, ceL)

    float qy[4], qa[4], qb[4], qc[4];
    float qeR[4] = {0,0,0,0}, qeL[4] = {0,0,0,0};
    LOADROW(r0 + 1, qy, qa, qb, qc, qeR, qeL)   // r0+1 < HH always (r0 <= 508)

    float acc = 0.0f;

    // horizontal(r0) — covers the next-row load latency
    {
        float hyR = __shfl_down_sync(FULLM, cy[0], 1);
        float haR = __shfl_down_sync(FULLM, ca[0], 1);
        float hbR = __shfl_down_sync(FULLM, cb[0], 1);
        float hcR = __shfl_down_sync(FULLM, cc[0], 1);
        if (lastLane) { hyR = ceR[0]; haR = ceR[1]; hbR = ceR[2]; hcR = ceR[3]; }
#pragma unroll
        for (int k = 0; k < 3; k++)
            acc += shift_term(ca[k], cb[k], cc[k], ca[k+1], cb[k+1], cc[k+1],
                              cy[k], cy[k+1], WXY1);
        if (hasR)
            acc += shift_term(ca[3], cb[3], cc[3], haR, hbR, hcR,
                              cy[3], hyR, WXY1);
    }

    // ---- pipelined main loop: iteration rr handles the pair (r0+rr, r0+rr+1) ----
#pragma unroll
    for (int rr = 0; rr < RPB; rr++) {
        const int r = r0 + rr;
        const bool haveDown = (r + 1 < HH);    // false only last block, rr=3

        // STEP 1: prefetch row r+2 (consumed next iteration)
        float py[4], pa[4], pb[4], pc[4];
        float peR[4] = {0,0,0,0}, peL[4] = {0,0,0,0};
        const bool doPref = (rr < RPB - 1) && (r + 2 < HH);
        if (doPref)
            LOADROW(r + 2, py, pa, pb, pc, peR, peL)

        if (haveDown) {
            // STEP 2: halos of next (raw loaded a full iteration ago)
            float nyR = __shfl_down_sync(FULLM, qy[0], 1);
            float naR = __shfl_down_sync(FULLM, qa[0], 1);
            float nbR = __shfl_down_sync(FULLM, qb[0], 1);
            float ncR = __shfl_down_sync(FULLM, qc[0], 1);
            if (lastLane) { nyR = qeR[0]; naR = qeR[1]; nbR = qeR[2]; ncR = qeR[3]; }
            float nyL = __shfl_up_sync(FULLM, qy[3], 1);
            float naL = __shfl_up_sync(FULLM, qa[3], 1);
            float nbL = __shfl_up_sync(FULLM, qb[3], 1);
            float ncL = __shfl_up_sync(FULLM, qc[3], 1);
            if (firstLane) { nyL = qeL[0]; naL = qeL[1]; nbL = qeL[2]; ncL = qeL[3]; }

            // STEP 3: vertical terms between cur(r) and next(r+1) — covers pref load
            // shift (1,0)
#pragma unroll
            for (int k = 0; k < 4; k++)
                acc += shift_term(ca[k], cb[k], cc[k], qa[k], qb[k], qc[k],
                                  cy[k], qy[k], WXY1);
            // shift (1,1)
#pragma unroll
            for (int k = 0; k < 3; k++)
                acc += shift_term(ca[k], cb[k], cc[k], qa[k+1], qb[k+1], qc[k+1],
                                  cy[k], qy[k+1], WXY2);
            if (hasR)
                acc += shift_term(ca[3], cb[3], cc[3], naR, nbR, ncR,
                                  cy[3], nyR, WXY2);
            // shift (1,-1)
#pragma unroll
            for (int k = 1; k < 4; k++)
                acc += shift_term(ca[k], cb[k], cc[k], qa[k-1], qb[k-1], qc[k-1],
                                  cy[k], qy[k-1], WXY2);
            if (hasL)
                acc += shift_term(ca[0], cb[0], cc[0], naL, nbL, ncL,
                                  cy[0], nyL, WXY2);

            // STEP 4: horizontal(next) — unless next row belongs to the next strip
            if (rr < RPB - 1) {
#pragma unroll
                for (int k = 0; k < 3; k++)
                    acc += shift_term(qa[k], qb[k], qc[k], qa[k+1], qb[k+1], qc[k+1],
                                      qy[k], qy[k+1], WXY1);
                if (hasR)
                    acc += shift_term(qa[3], qb[3], qc[3], naR, nbR, ncR,
                                      qy[3], nyR, WXY1);
            }
        }

        // STEP 5: roll  cur <- next, next <- pref
        if (rr < RPB - 1) {
#pragma unroll
            for (int k = 0; k < 4; k++) {
                cy[k] = qy[k]; ca[k] = qa[k]; cb[k] = qb[k]; cc[k] = qc[k];
                qy[k] = py[k]; qa[k] = pa[k]; qb[k] = pb[k]; qc[k] = pc[k];
                qeR[k] = peR[k]; qeL[k] = peL[k];
            }
        }
    }
#undef LOADROW

    // ---- block reduction ----
#pragma unroll
    for (int o = 16; o > 0; o >>= 1)
        acc += __shfl_down_sync(FULLM, acc, o);

    __shared__ float sm[NTHR / 32];
    if (lane == 0) sm[tid >> 5] = acc;
    __syncthreads();
    if (tid == 0) {
        float v = sm[0] + sm[1] + sm[2] + sm[3];
        const float SCALE = 1.0f / 16777216.0f;    // 1/(H*W*B*4), WEIGHT=1
        atomicAdd(out, v * SCALE);
    }
}

__global__ void zero_out_kernel(float* out) {
    if (threadIdx.x == 0) out[0] = 0.0f;
}

extern "C" void kernel_launch(void* const* d_in, const int* in_sizes, int n_in,
                              void* d_out, int out_size) {
    const float* ypr  = (const float*)d_in[0];   // y_pr  (16,2,512,512)
    // d_in[1] = y_gt (unused by the reference)
    const float* img  = (const float*)d_in[2];   // image (16,3,512,512)
    const int*   icls = (const int*)d_in[3];     // image_class (16,)
    float* out = (float*)d_out;

    zero_out_kernel<<<1, 32>>>(out);
    dim3 grid(GRIDX, BB);
    crf_loss_kernel<<<grid, NTHR>>>(ypr, img, icls, out);
}